// round 3
// baseline (speedup 1.0000x reference)
#include <cuda_runtime.h>

// Problem constants (fixed by the reference)
#define BB   256
#define TT   16384
#define WIN  5
#define HID  5
#define NN   (TT - WIN)   // 16379

// ---- Phase A (lag-correlation) config ----
#define G     8            // b-groups
#define BPG   (BB / G)     // 32 b per group
#define TPT   4            // t positions per thread
#define TPB   256
#define TBLK  (TPT * TPB)  // 1024 t per block
#define NBX   (TT / TBLK)  // 16 blocks in t

#define TSTRIDE 16416      // padded t-stride for scratch (16384 + 32)

// Scratch: [G][7 stats][TSTRIDE]; stats 0..5 = C_d (lag d), 6 = mean-sum.
// 8 * 7 * 16416 * 4B = 3.68 MB.
__device__ float g_stat[G * 7 * TSTRIDE];

// ============================ Phase A =====================================
// C_d[t] = sum_b x[b,t] * x[b,t+d]  (d = 0..5),  m[t] = sum_b x[b,t]
__global__ void __launch_bounds__(TPB)
llsa_corr_kernel(const float* __restrict__ series)
{
    const int t0 = blockIdx.x * TBLK + threadIdx.x * TPT;
    const int g  = blockIdx.y;

    float acc[7][TPT];
#pragma unroll
    for (int s = 0; s < 7; s++)
#pragma unroll
        for (int i = 0; i < TPT; i++) acc[s][i] = 0.0f;

    const bool fast = (t0 + 12 <= TT);
    const float* __restrict__ row = series + (size_t)(g * BPG) * TT + t0;

    for (int bb = 0; bb < BPG; bb++, row += TT) {
        float x[12];
        if (fast) {
            const float4* p = reinterpret_cast<const float4*>(row);
            float4 v0 = __ldg(&p[0]);
            float4 v1 = __ldg(&p[1]);
            float4 v2 = __ldg(&p[2]);
            x[0]=v0.x; x[1]=v0.y; x[2]=v0.z;  x[3]=v0.w;
            x[4]=v1.x; x[5]=v1.y; x[6]=v1.z;  x[7]=v1.w;
            x[8]=v2.x; x[9]=v2.y; x[10]=v2.z; x[11]=v2.w;
        } else {
            // only last 2 threads of the last t-block
#pragma unroll
            for (int j = 0; j < 12; j++)
                x[j] = (t0 + j < TT) ? __ldg(&row[j]) : 0.0f;
        }

#pragma unroll
        for (int i = 0; i < TPT; i++) {
            acc[6][i] += x[i];
#pragma unroll
            for (int d = 0; d < 6; d++)
                acc[d][i] = fmaf(x[i], x[i + d], acc[d][i]);
        }
    }

    // Vector stores: t0 is a multiple of 4, TSTRIDE is a multiple of 4.
#pragma unroll
    for (int s = 0; s < 7; s++) {
        float4 v = make_float4(acc[s][0], acc[s][1], acc[s][2], acc[s][3]);
        *reinterpret_cast<float4*>(&g_stat[(size_t)(g * 7 + s) * TSTRIDE + t0]) = v;
    }
}

// ============================ Phase B =====================================
// Reduce stats over G, build M = sum_h r_h r_h^T, combine, diffs + mask.
#define NK 262   // stats t-range needed per block: n0 .. n0+261

__device__ __forceinline__ int triidx(int i, int j) {
    // upper-triangular index in 7x7, i <= j
    return 7 * i - (i * (i - 1)) / 2 + (j - i);
}

__global__ void __launch_bounds__(TPB)
llsa_loss_kernel(const float* __restrict__ weight,
                 const float* __restrict__ bias,
                 const float* __restrict__ thr_p,
                 float* __restrict__ out)
{
    __shared__ float R[7][NK + 2];  // reduced stats
    __shared__ float sM[28];        // folded M (off-diag pre-doubled)
    __shared__ float sloss[TPB + 1];

    const int tid = threadIdx.x;
    const int n0  = blockIdx.x * TPB;

    // Cooperative G-reduction of the 7 stat rows for t = n0 .. n0+261.
    for (int e = tid; e < 7 * NK; e += TPB) {
        const int s = e / NK;
        const int k = e - s * NK;
        const int t = n0 + k;
        float v = 0.0f;
        if (t < TT) {
#pragma unroll
            for (int g = 0; g < G; g++)
                v += g_stat[(size_t)(g * 7 + s) * TSTRIDE + t];
        }
        R[s][k] = v;
    }

    // Warp 0 builds M: r_h = (W[h,0..4], 0, b_h) with r_h[1+h] -= 1.
    if (tid < 28) {
        int i = 0, j = tid;
        while (j >= 7 - i) { j -= 7 - i; i++; }
        j += i;                       // now (i, j) with i <= j

        float m = 0.0f;
#pragma unroll
        for (int h = 0; h < HID; h++) {
            float ri = (i < WIN) ? __ldg(&weight[h * WIN + i]) : 0.0f;
            float rj = (j < WIN) ? __ldg(&weight[h * WIN + j]) : 0.0f;
            if (i == 1 + h) ri -= 1.0f;
            if (j == 1 + h) rj -= 1.0f;
            if (i == 6) ri = __ldg(&bias[h]);
            if (j == 6) rj = __ldg(&bias[h]);
            m = fmaf(ri, rj, m);
        }
        sM[tid] = (i == j) ? m : 2.0f * m;
    }
    __syncthreads();

    // loss[n0+k] = (1/(B*H)) * sum_{i<=j} Mfold_ij * Z_ij
    auto compute_loss = [&](int k) -> float {
        float s = sM[triidx(6, 6)] * (float)BB;
#pragma unroll
        for (int i = 0; i < 6; i++)
            s = fmaf(sM[triidx(i, 6)], R[6][k + i], s);   // mean terms
#pragma unroll
        for (int i = 0; i < 6; i++)
            s = fmaf(sM[triidx(i, i)], R[0][k + i], s);   // diagonal (lag 0)
#pragma unroll
        for (int i = 0; i < 6; i++)
#pragma unroll
            for (int j = i + 1; j < 6; j++)
                s = fmaf(sM[triidx(i, j)], R[j - i][k + i], s);
        return s * (1.0f / (float)(BB * HID));
    };

    const int n = n0 + tid;
    float L = 0.0f;
    if (n < NN) L = compute_loss(tid);
    sloss[tid] = L;
    if (tid == 0) {
        const int n2 = n0 + TPB;
        sloss[TPB] = (n2 < NN) ? compute_loss(TPB) : 0.0f;
    }
    __syncthreads();

    if (n < NN) {
        out[n] = L;
        if (n < NN - 1) {
            const float d = fabsf(sloss[tid + 1] - L);
            out[NN + n] = d;
            out[2 * NN - 1 + n] = (d > __ldg(thr_p)) ? 1.0f : 0.0f;
        }
    }
}

// ============================ Launch =====================================
extern "C" void kernel_launch(void* const* d_in, const int* in_sizes, int n_in,
                              void* d_out, int out_size)
{
    const float* series = (const float*)d_in[0];
    const float* weight = (const float*)d_in[1];
    const float* bias   = (const float*)d_in[2];
    const float* thr    = (const float*)d_in[3];
    float* out = (float*)d_out;

    dim3 gridA(NBX, G);
    llsa_corr_kernel<<<gridA, TPB>>>(series);

    const int nblkB = (NN + TPB - 1) / TPB;   // 64
    llsa_loss_kernel<<<nblkB, TPB>>>(weight, bias, thr, out);
}

// round 4
// speedup vs baseline: 1.0259x; 1.0259x over previous
#include <cuda_runtime.h>

// Problem constants (fixed by the reference)
#define BB   256
#define TT   16384
#define WIN  5
#define HID  5
#define NN   (TT - WIN)   // 16379

// ---- Phase A config ----
#define G       8               // b-groups
#define BPG     (BB / G)        // 32 rows per group
#define TCHUNK  1024            // t per block
#define NBX     (TT / TCHUNK)   // 16
#define TPT     4               // t per thread (256 threads * 4 = 1024)
#define TPB     256
#define SROWS   8               // rows staged in smem at once
#define ROWF    (TCHUNK + 16)   // padded row buffer (floats)
#define ROWV    ((TCHUNK + 16) / 4)  // 260 float4 per row
#define NT4     (TT / 4)        // 4096 t4 slots

// Scratch layout: [stat s][t4][group g][4 floats] -> 7*4096*8*4 = 3.67 MB
__device__ float g_stat[7 * NT4 * G * 4];

// ============================ Phase A =====================================
// C_d[t] = sum_b x[b,t]*x[b,t+d] (d=0..5),  m[t] = sum_b x[b,t]
__global__ void __launch_bounds__(TPB)
llsa_corr_kernel(const float* __restrict__ series)
{
    __shared__ float sx[SROWS][ROWF];

    const int tid = threadIdx.x;
    const int g   = blockIdx.y;
    const int t0  = blockIdx.x * TCHUNK;
    const int tl  = tid * TPT;            // local t base (16B aligned)

    float acc[7][TPT];
#pragma unroll
    for (int s = 0; s < 7; s++)
#pragma unroll
        for (int i = 0; i < TPT; i++) acc[s][i] = 0.0f;

    for (int stage = 0; stage < BPG / SROWS; stage++) {
        __syncthreads();   // protect previous stage's reads
        // Cooperative load: SROWS rows x ROWV float4, coalesced.
        for (int j = tid; j < SROWS * ROWV; j += TPB) {
            const int r  = j / ROWV;
            const int c  = j - r * ROWV;
            const int b  = g * BPG + stage * SROWS + r;
            const int tg = t0 + c * 4;
            float4 v;
            if (tg + 3 < TT) {
                v = __ldg(reinterpret_cast<const float4*>(
                        series + (size_t)b * TT + tg));
            } else {
                const float* row = series + (size_t)b * TT;
                v.x = (tg     < TT) ? __ldg(&row[tg])     : 0.0f;
                v.y = (tg + 1 < TT) ? __ldg(&row[tg + 1]) : 0.0f;
                v.z = (tg + 2 < TT) ? __ldg(&row[tg + 2]) : 0.0f;
                v.w = (tg + 3 < TT) ? __ldg(&row[tg + 3]) : 0.0f;
            }
            *reinterpret_cast<float4*>(&sx[r][c * 4]) = v;
        }
        __syncthreads();

#pragma unroll
        for (int r = 0; r < SROWS; r++) {
            const float4 a0 = *reinterpret_cast<const float4*>(&sx[r][tl]);
            const float4 a1 = *reinterpret_cast<const float4*>(&sx[r][tl + 4]);
            const float4 a2 = *reinterpret_cast<const float4*>(&sx[r][tl + 8]);
            const float x[9] = {a0.x, a0.y, a0.z, a0.w,
                                a1.x, a1.y, a1.z, a1.w, a2.x};
#pragma unroll
            for (int i = 0; i < TPT; i++) {
                acc[6][i] += x[i];
#pragma unroll
                for (int d = 0; d < 6; d++)
                    acc[d][i] = fmaf(x[i], x[i + d], acc[d][i]);
            }
        }
    }

    // Store: one float4 per stat at [s][t4][g][0..3]
    const int t4 = blockIdx.x * (TCHUNK / 4) + tid;   // 0..4095
#pragma unroll
    for (int s = 0; s < 7; s++) {
        float4 v = make_float4(acc[s][0], acc[s][1], acc[s][2], acc[s][3]);
        *reinterpret_cast<float4*>(
            &g_stat[(((size_t)s * NT4 + t4) * G + g) * 4]) = v;
    }
}

// ============================ Phase B =====================================
#define NPB2  256          // n per block
#define KT4   66           // t4 slots needed: ceil(262/4) + align
#define NKF   (KT4 * 4)    // 264 floats of reduced stats per s

__device__ __forceinline__ int triidx(int i, int j) {
    return 7 * i - (i * (i - 1)) / 2 + (j - i);   // upper-tri 7x7, i <= j
}

__global__ void __launch_bounds__(TPB)
llsa_loss_kernel(const float* __restrict__ weight,
                 const float* __restrict__ bias,
                 const float* __restrict__ thr_p,
                 float* __restrict__ out)
{
    __shared__ float R[7][NKF + 4];
    __shared__ float sM[28];
    __shared__ float sloss[NPB2 + 1];

    const int tid = threadIdx.x;
    const int n0  = blockIdx.x * NPB2;
    const int t40 = n0 / 4;

    // G-reduce: job = (s, k); 8 contiguous float4 loads (one 128B burst).
    for (int job = tid; job < 7 * KT4; job += TPB) {
        const int s  = job / KT4;
        const int k  = job - s * KT4;
        const int t4 = t40 + k;
        float4 r = make_float4(0.f, 0.f, 0.f, 0.f);
        if (t4 < NT4) {
            const float4* p = reinterpret_cast<const float4*>(
                &g_stat[((size_t)s * NT4 + t4) * G * 4]);
#pragma unroll
            for (int gg = 0; gg < G; gg++) {
                float4 v = p[gg];
                r.x += v.x; r.y += v.y; r.z += v.z; r.w += v.w;
            }
        }
        *reinterpret_cast<float4*>(&R[s][k * 4]) = r;
    }

    // Build folded M (28 threads): r_h = (W[h,0..4], 0, b_h), r_h[1+h] -= 1.
    if (tid < 28) {
        int i = 0, j = tid;
        while (j >= 7 - i) { j -= 7 - i; i++; }
        j += i;
        float m = 0.0f;
#pragma unroll
        for (int h = 0; h < HID; h++) {
            float ri = (i < WIN) ? __ldg(&weight[h * WIN + i]) : 0.0f;
            float rj = (j < WIN) ? __ldg(&weight[h * WIN + j]) : 0.0f;
            if (i == 1 + h) ri -= 1.0f;
            if (j == 1 + h) rj -= 1.0f;
            if (i == 6) ri = __ldg(&bias[h]);
            if (j == 6) rj = __ldg(&bias[h]);
            m = fmaf(ri, rj, m);
        }
        sM[tid] = (i == j) ? m : 2.0f * m;
    }
    __syncthreads();

    auto compute_loss = [&](int k) -> float {
        float s = sM[triidx(6, 6)] * (float)BB;
#pragma unroll
        for (int i = 0; i < 6; i++)
            s = fmaf(sM[triidx(i, 6)], R[6][k + i], s);   // mean terms
#pragma unroll
        for (int i = 0; i < 6; i++)
            s = fmaf(sM[triidx(i, i)], R[0][k + i], s);   // diag (lag 0)
#pragma unroll
        for (int i = 0; i < 6; i++)
#pragma unroll
            for (int j = i + 1; j < 6; j++)
                s = fmaf(sM[triidx(i, j)], R[j - i][k + i], s);
        return s * (1.0f / (float)(BB * HID));
    };

    const int n = n0 + tid;
    float L = 0.0f;
    if (n < NN) L = compute_loss(tid);
    sloss[tid] = L;
    if (tid == 0)
        sloss[NPB2] = (n0 + NPB2 < NN) ? compute_loss(NPB2) : 0.0f;
    __syncthreads();

    if (n < NN) {
        out[n] = L;
        if (n < NN - 1) {
            const float d = fabsf(sloss[tid + 1] - L);
            out[NN + n] = d;
            out[2 * NN - 1 + n] = (d > __ldg(thr_p)) ? 1.0f : 0.0f;
        }
    }
}

// ============================ Launch =====================================
extern "C" void kernel_launch(void* const* d_in, const int* in_sizes, int n_in,
                              void* d_out, int out_size)
{
    const float* series = (const float*)d_in[0];
    const float* weight = (const float*)d_in[1];
    const float* bias   = (const float*)d_in[2];
    const float* thr    = (const float*)d_in[3];
    float* out = (float*)d_out;

    dim3 gridA(NBX, G);
    llsa_corr_kernel<<<gridA, TPB>>>(series);

    const int nblkB = (NN + NPB2 - 1) / NPB2;   // 64
    llsa_loss_kernel<<<nblkB, TPB>>>(weight, bias, thr, out);
}

// round 5
// speedup vs baseline: 1.2746x; 1.2424x over previous
#include <cuda_runtime.h>

// Problem constants (fixed by the reference)
#define BB   256
#define TT   16384
#define WIN  5
#define HID  5
#define NN   (TT - WIN)   // 16379

// ---- Fused kernel config ----
#define TPB    256
#define NPB    120                          // n per block
#define NBLK   ((NN + NPB - 1) / NPB)       // 137 blocks
#define ROWB   136                          // floats of x per row: n0 .. n0+132 (pad to 34*4)
#define T4     (ROWB / 4)                   // 34 float4 per row
#define SROWS  32                           // rows staged per round (4 per rowgroup)
#define NROUND 8                            // 8 rounds * 4 rows = 32 rows per rowgroup
#define NWARP  8                            // rowgroups (= warps)
#define NSTAT  7                            // C_0..C_5, mean
#define STATF  (NSTAT * ROWB)               // 952 floats of stats

__device__ __forceinline__ int triidx(int i, int j) {
    return 7 * i - (i * (i - 1)) / 2 + (j - i);   // upper-tri 7x7, i <= j
}

__global__ void __launch_bounds__(TPB)
llsa_fused_kernel(const float* __restrict__ series,
                  const float* __restrict__ weight,
                  const float* __restrict__ bias,
                  const float* __restrict__ thr_p,
                  float* __restrict__ out)
{
    // Pool aliased across phases:
    //   phase 1 (main loop):  sx[SROWS][ROWB]            = 4352 floats
    //   phase 2 (reduction):  swred[NWARP][NSTAT][ROWB]  = 7616 floats
    __shared__ float pool[NWARP * STATF];        // 30.5 KB
    __shared__ float R[NSTAT][ROWB + 4];         // reduced stats
    __shared__ float sM[28];
    __shared__ float sloss[NPB + 2];

    const int tid  = threadIdx.x;
    const int slot = tid & 31;        // t4-slot 0..31  -> t = n0 + slot*4 .. +3
    const int rg   = tid >> 5;        // rowgroup/warp 0..7 -> rows rg*32 .. rg*32+31
    const int n0   = blockIdx.x * NPB;

    float (*sx)[ROWB] = reinterpret_cast<float(*)[ROWB]>(pool);

    float acc[NSTAT][4];
#pragma unroll
    for (int s = 0; s < NSTAT; s++)
#pragma unroll
        for (int i = 0; i < 4; i++) acc[s][i] = 0.0f;

    const int tl = slot * 4;          // local t base; needs sx[tl .. tl+11]

    for (int rnd = 0; rnd < NROUND; rnd++) {
        __syncthreads();              // previous round's reads done
        // Stage SROWS rows: slot i holds row b = (i>>2)*32 + rnd*4 + (i&3).
        for (int e = tid; e < SROWS * T4; e += TPB) {
            const int i = e / T4;
            const int c = e - i * T4;
            const int b = ((i >> 2) << 5) + (rnd << 2) + (i & 3);
            const int tg = n0 + c * 4;
            float4 v;
            if (tg + 3 < TT) {
                v = __ldg(reinterpret_cast<const float4*>(
                        series + (size_t)b * TT + tg));
            } else {
                const float* row = series + (size_t)b * TT;
                v.x = (tg     < TT) ? __ldg(&row[tg])     : 0.0f;
                v.y = (tg + 1 < TT) ? __ldg(&row[tg + 1]) : 0.0f;
                v.z = (tg + 2 < TT) ? __ldg(&row[tg + 2]) : 0.0f;
                v.w = (tg + 3 < TT) ? __ldg(&row[tg + 3]) : 0.0f;
            }
            *reinterpret_cast<float4*>(&sx[i][c * 4]) = v;
        }
        __syncthreads();

        // Each warp consumes its own 4 rows (whole warp reads same row: broadcast-friendly).
#pragma unroll
        for (int j = 0; j < 4; j++) {
            const float* rowp = sx[(rg << 2) + j];
            const float4 a0 = *reinterpret_cast<const float4*>(&rowp[tl]);
            const float4 a1 = *reinterpret_cast<const float4*>(&rowp[tl + 4]);
            const float4 a2 = *reinterpret_cast<const float4*>(&rowp[tl + 8]);
            const float x[9] = {a0.x, a0.y, a0.z, a0.w,
                                a1.x, a1.y, a1.z, a1.w, a2.x};
#pragma unroll
            for (int i = 0; i < 4; i++) {
                acc[6][i] += x[i];
#pragma unroll
                for (int d = 0; d < 6; d++)
                    acc[d][i] = fmaf(x[i], x[i + d], acc[d][i]);
            }
        }
    }

    // ---- Cross-warp stat reduction via aliased pool ----
    __syncthreads();                  // all sx reads done; pool reusable
#pragma unroll
    for (int s = 0; s < NSTAT; s++)
#pragma unroll
        for (int i = 0; i < 4; i++)
            pool[rg * STATF + s * ROWB + tl + i] = acc[s][i];
    __syncthreads();

    for (int e = tid; e < STATF; e += TPB) {
        float v = 0.0f;
#pragma unroll
        for (int w = 0; w < NWARP; w++)
            v += pool[w * STATF + e];
        const int s = e / ROWB;
        const int k = e - s * ROWB;
        R[s][k] = v;
    }

    // ---- Build folded M: r_h = (W[h,0..4], 0, b_h), r_h[1+h] -= 1 ----
    if (tid < 28) {
        int i = 0, j = tid;
        while (j >= 7 - i) { j -= 7 - i; i++; }
        j += i;
        float m = 0.0f;
#pragma unroll
        for (int h = 0; h < HID; h++) {
            float ri = (i < WIN) ? __ldg(&weight[h * WIN + i]) : 0.0f;
            float rj = (j < WIN) ? __ldg(&weight[h * WIN + j]) : 0.0f;
            if (i == 1 + h) ri -= 1.0f;
            if (j == 1 + h) rj -= 1.0f;
            if (i == 6) ri = __ldg(&bias[h]);
            if (j == 6) rj = __ldg(&bias[h]);
            m = fmaf(ri, rj, m);
        }
        sM[tid] = (i == j) ? m : 2.0f * m;
    }
    __syncthreads();

    // ---- Combine: loss[n0+k] = (1/(B*H)) * sum_{i<=j} Mfold_ij * Z_ij ----
    auto compute_loss = [&](int k) -> float {
        float s = sM[triidx(6, 6)] * (float)BB;
#pragma unroll
        for (int i = 0; i < 6; i++)
            s = fmaf(sM[triidx(i, 6)], R[6][k + i], s);   // mean terms
#pragma unroll
        for (int i = 0; i < 6; i++)
            s = fmaf(sM[triidx(i, i)], R[0][k + i], s);   // diagonal (lag 0)
#pragma unroll
        for (int i = 0; i < 6; i++)
#pragma unroll
            for (int j = i + 1; j < 6; j++)
                s = fmaf(sM[triidx(i, j)], R[j - i][k + i], s);
        return s * (1.0f / (float)(BB * HID));
    };

    // Compute NPB losses + one neighbor (k = NPB) for the cross-block diff.
    float L = 0.0f;
    const int n = n0 + tid;
    if (tid <= NPB && n < NN) L = compute_loss(tid);
    if (tid <= NPB) sloss[tid] = L;
    __syncthreads();

    if (tid < NPB && n < NN) {
        out[n] = L;
        if (n < NN - 1) {
            const float d = fabsf(sloss[tid + 1] - L);
            out[NN + n] = d;
            out[2 * NN - 1 + n] = (d > __ldg(thr_p)) ? 1.0f : 0.0f;
        }
    }
}

extern "C" void kernel_launch(void* const* d_in, const int* in_sizes, int n_in,
                              void* d_out, int out_size)
{
    const float* series = (const float*)d_in[0];
    const float* weight = (const float*)d_in[1];
    const float* bias   = (const float*)d_in[2];
    const float* thr    = (const float*)d_in[3];
    float* out = (float*)d_out;

    llsa_fused_kernel<<<NBLK, TPB>>>(series, weight, bias, thr, out);
}

// round 7
// speedup vs baseline: 1.2770x; 1.0019x over previous
#include <cuda_runtime.h>

// Problem constants (fixed by the reference)
#define BB   256
#define TT   16384
#define WIN  5
#define HID  5
#define NN   (TT - WIN)   // 16379

// ---- Fused kernel config ----
#define TPB    256
#define NPB    120                          // n per block
#define NBLK   ((NN + NPB - 1) / NPB)       // 137 blocks
#define ROWB   136                          // floats of x per row: n0 .. n0+132 (pad to 34*4)
#define T4     (ROWB / 4)                   // 34 float4 per row
#define SROWS  32                           // rows staged per round (4 per rowgroup)
#define NROUND 8                            // 8 rounds * 4 rows = 32 rows per rowgroup
#define NWARP  8                            // rowgroups (= warps)
#define NSTAT  7                            // C_0..C_5, mean
#define STATF  (NSTAT * ROWB)               // 952 floats of stats

__device__ __forceinline__ int triidx(int i, int j) {
    return 7 * i - (i * (i - 1)) / 2 + (j - i);   // upper-tri 7x7, i <= j
}

__global__ void __launch_bounds__(TPB)
llsa_fused_kernel(const float* __restrict__ series,
                  const float* __restrict__ weight,
                  const float* __restrict__ bias,
                  const float* __restrict__ thr_p,
                  float* __restrict__ out)
{
    // Pool aliased across phases:
    //   phase 1 (main loop):  sx[SROWS][ROWB]            = 4352 floats
    //   phase 2 (reduction):  swred[NWARP][NSTAT][ROWB]  = 7616 floats
    __shared__ float pool[NWARP * STATF];        // 30.5 KB
    __shared__ float R[NSTAT][ROWB + 4];         // reduced stats
    __shared__ float sM[28];
    __shared__ float sloss[NPB + 2];

    const int tid  = threadIdx.x;
    const int slot = tid & 31;        // t4-slot 0..31  -> t = n0 + slot*4 .. +3
    const int rg   = tid >> 5;        // rowgroup/warp 0..7 -> rows rg*32 .. rg*32+31
    const int n0   = blockIdx.x * NPB;

    float (*sx)[ROWB] = reinterpret_cast<float(*)[ROWB]>(pool);

    float acc[NSTAT][4];
#pragma unroll
    for (int s = 0; s < NSTAT; s++)
#pragma unroll
        for (int i = 0; i < 4; i++) acc[s][i] = 0.0f;

    const int tl = slot * 4;          // local t base; needs sx[tl .. tl+11]

    for (int rnd = 0; rnd < NROUND; rnd++) {
        __syncthreads();              // previous round's reads done
        // Stage SROWS rows: slot i holds row b = (i>>2)*32 + rnd*4 + (i&3).
        for (int e = tid; e < SROWS * T4; e += TPB) {
            const int i = e / T4;
            const int c = e - i * T4;
            const int b = ((i >> 2) << 5) + (rnd << 2) + (i & 3);
            const int tg = n0 + c * 4;
            float4 v;
            if (tg + 3 < TT) {
                v = __ldg(reinterpret_cast<const float4*>(
                        series + (size_t)b * TT + tg));
            } else {
                const float* row = series + (size_t)b * TT;
                v.x = (tg     < TT) ? __ldg(&row[tg])     : 0.0f;
                v.y = (tg + 1 < TT) ? __ldg(&row[tg + 1]) : 0.0f;
                v.z = (tg + 2 < TT) ? __ldg(&row[tg + 2]) : 0.0f;
                v.w = (tg + 3 < TT) ? __ldg(&row[tg + 3]) : 0.0f;
            }
            *reinterpret_cast<float4*>(&sx[i][c * 4]) = v;
        }
        __syncthreads();

        // Each warp consumes its own 4 rows (whole warp reads same row: broadcast-friendly).
#pragma unroll
        for (int j = 0; j < 4; j++) {
            const float* rowp = sx[(rg << 2) + j];
            const float4 a0 = *reinterpret_cast<const float4*>(&rowp[tl]);
            const float4 a1 = *reinterpret_cast<const float4*>(&rowp[tl + 4]);
            const float4 a2 = *reinterpret_cast<const float4*>(&rowp[tl + 8]);
            const float x[9] = {a0.x, a0.y, a0.z, a0.w,
                                a1.x, a1.y, a1.z, a1.w, a2.x};
#pragma unroll
            for (int i = 0; i < 4; i++) {
                acc[6][i] += x[i];
#pragma unroll
                for (int d = 0; d < 6; d++)
                    acc[d][i] = fmaf(x[i], x[i + d], acc[d][i]);
            }
        }
    }

    // ---- Cross-warp stat reduction via aliased pool ----
    __syncthreads();                  // all sx reads done; pool reusable
#pragma unroll
    for (int s = 0; s < NSTAT; s++)
#pragma unroll
        for (int i = 0; i < 4; i++)
            pool[rg * STATF + s * ROWB + tl + i] = acc[s][i];
    __syncthreads();

    for (int e = tid; e < STATF; e += TPB) {
        float v = 0.0f;
#pragma unroll
        for (int w = 0; w < NWARP; w++)
            v += pool[w * STATF + e];
        const int s = e / ROWB;
        const int k = e - s * ROWB;
        R[s][k] = v;
    }

    // ---- Build folded M: r_h = (W[h,0..4], 0, b_h), r_h[1+h] -= 1 ----
    if (tid < 28) {
        int i = 0, j = tid;
        while (j >= 7 - i) { j -= 7 - i; i++; }
        j += i;
        float m = 0.0f;
#pragma unroll
        for (int h = 0; h < HID; h++) {
            float ri = (i < WIN) ? __ldg(&weight[h * WIN + i]) : 0.0f;
            float rj = (j < WIN) ? __ldg(&weight[h * WIN + j]) : 0.0f;
            if (i == 1 + h) ri -= 1.0f;
            if (j == 1 + h) rj -= 1.0f;
            if (i == 6) ri = __ldg(&bias[h]);
            if (j == 6) rj = __ldg(&bias[h]);
            m = fmaf(ri, rj, m);
        }
        sM[tid] = (i == j) ? m : 2.0f * m;
    }
    __syncthreads();

    // ---- Combine: loss[n0+k] = (1/(B*H)) * sum_{i<=j} Mfold_ij * Z_ij ----
    auto compute_loss = [&](int k) -> float {
        float s = sM[triidx(6, 6)] * (float)BB;
#pragma unroll
        for (int i = 0; i < 6; i++)
            s = fmaf(sM[triidx(i, 6)], R[6][k + i], s);   // mean terms
#pragma unroll
        for (int i = 0; i < 6; i++)
            s = fmaf(sM[triidx(i, i)], R[0][k + i], s);   // diagonal (lag 0)
#pragma unroll
        for (int i = 0; i < 6; i++)
#pragma unroll
            for (int j = i + 1; j < 6; j++)
                s = fmaf(sM[triidx(i, j)], R[j - i][k + i], s);
        return s * (1.0f / (float)(BB * HID));
    };

    // Compute NPB losses + one neighbor (k = NPB) for the cross-block diff.
    float L = 0.0f;
    const int n = n0 + tid;
    if (tid <= NPB && n < NN) L = compute_loss(tid);
    if (tid <= NPB) sloss[tid] = L;
    __syncthreads();

    if (tid < NPB && n < NN) {
        out[n] = L;
        if (n < NN - 1) {
            const float d = fabsf(sloss[tid + 1] - L);
            out[NN + n] = d;
            out[2 * NN - 1 + n] = (d > __ldg(thr_p)) ? 1.0f : 0.0f;
        }
    }
}

extern "C" void kernel_launch(void* const* d_in, const int* in_sizes, int n_in,
                              void* d_out, int out_size)
{
    const float* series = (const float*)d_in[0];
    const float* weight = (const float*)d_in[1];
    const float* bias   = (const float*)d_in[2];
    const float* thr    = (const float*)d_in[3];
    float* out = (float*)d_out;

    llsa_fused_kernel<<<NBLK, TPB>>>(series, weight, bias, thr, out);
}

// round 8
// speedup vs baseline: 1.6062x; 1.2578x over previous
#include <cuda_runtime.h>

// Problem constants (fixed by the reference)
#define BB   256
#define TT   16384
#define WIN  5
#define HID  5
#define NN   (TT - WIN)   // 16379

// ---- Fused kernel config ----
#define TPB    256
#define NPB    120                          // n per block
#define NBLK   ((NN + NPB - 1) / NPB)       // 137 blocks
#define ROWB   136                          // stat row length (padded)
#define RPW    32                           // rows per warp (8 warps * 32 = 256 = BB)
#define NWARP  8
#define NSTAT  7                            // C_0..C_5, mean
#define STATF  (NSTAT * ROWB)               // 952 floats

__device__ __forceinline__ int triidx(int i, int j) {
    return 7 * i - (i * (i - 1)) / 2 + (j - i);   // upper-tri 7x7, i <= j
}

__global__ void __launch_bounds__(TPB)
llsa_fused_kernel(const float* __restrict__ series,
                  const float* __restrict__ weight,
                  const float* __restrict__ bias,
                  const float* __restrict__ thr_p,
                  float* __restrict__ out)
{
    __shared__ float pool[NWARP * STATF];    // per-warp stat partials (30.5 KB)
    __shared__ float R[NSTAT][ROWB + 4];     // reduced stats
    __shared__ float sM[28];
    __shared__ float sloss[NPB + 2];

    const int tid  = threadIdx.x;
    const int slot = tid & 31;        // t4-slot: t-local = slot*4 .. +3
    const int rg   = tid >> 5;        // warp id -> rows rg*32 .. rg*32+31
    const int n0   = blockIdx.x * NPB;
    const int tl   = slot * 4;

    float acc[NSTAT][4];
#pragma unroll
    for (int s = 0; s < NSTAT; s++)
#pragma unroll
        for (int i = 0; i < 4; i++) acc[s][i] = 0.0f;

    // ---- Main loop: direct gmem, no smem, no syncs. ----
    // Thread reads x[t .. t+11] for t = n0 + tl, over its warp's 32 rows.
    const float* base = series + (size_t)(rg * RPW) * TT + (n0 + tl);
    const bool fast = (n0 + tl + 12 <= TT);   // float4 x3 fully in-bounds

    if (fast) {
#pragma unroll 4
        for (int r = 0; r < RPW; r++) {
            const float* rp = base + (size_t)r * TT;
            const float4 a0 = *reinterpret_cast<const float4*>(rp);
            const float4 a1 = *reinterpret_cast<const float4*>(rp + 4);
            const float4 a2 = *reinterpret_cast<const float4*>(rp + 8);
            const float x[9] = {a0.x, a0.y, a0.z, a0.w,
                                a1.x, a1.y, a1.z, a1.w, a2.x};
#pragma unroll
            for (int i = 0; i < 4; i++) {
                acc[6][i] += x[i];
#pragma unroll
                for (int d = 0; d < 6; d++)
                    acc[d][i] = fmaf(x[i], x[i + d], acc[d][i]);
            }
        }
    } else {
        // Last block's high slots only: scalar guarded loads.
        for (int r = 0; r < RPW; r++) {
            const float* rp = base + (size_t)r * TT;
            float x[12];
#pragma unroll
            for (int j = 0; j < 12; j++)
                x[j] = (n0 + tl + j < TT) ? rp[j] : 0.0f;
#pragma unroll
            for (int i = 0; i < 4; i++) {
                acc[6][i] += x[i];
#pragma unroll
                for (int d = 0; d < 6; d++)
                    acc[d][i] = fmaf(x[i], x[i + d], acc[d][i]);
            }
        }
    }

    // ---- Cross-warp stat reduction ----
#pragma unroll
    for (int s = 0; s < NSTAT; s++)
#pragma unroll
        for (int i = 0; i < 4; i++)
            pool[rg * STATF + s * ROWB + tl + i] = acc[s][i];
    __syncthreads();

    for (int e = tid; e < NSTAT * 128; e += TPB) {   // only k<128 is consumed
        const int s = e >> 7;
        const int k = e & 127;
        float v = 0.0f;
#pragma unroll
        for (int w = 0; w < NWARP; w++)
            v += pool[w * STATF + s * ROWB + k];
        R[s][k] = v;
    }

    // ---- Build folded M: r_h = (W[h,0..4], 0, b_h), r_h[1+h] -= 1 ----
    if (tid < 28) {
        int i = 0, j = tid;
        while (j >= 7 - i) { j -= 7 - i; i++; }
        j += i;
        float m = 0.0f;
#pragma unroll
        for (int h = 0; h < HID; h++) {
            float ri = (i < WIN) ? __ldg(&weight[h * WIN + i]) : 0.0f;
            float rj = (j < WIN) ? __ldg(&weight[h * WIN + j]) : 0.0f;
            if (i == 1 + h) ri -= 1.0f;
            if (j == 1 + h) rj -= 1.0f;
            if (i == 6) ri = __ldg(&bias[h]);
            if (j == 6) rj = __ldg(&bias[h]);
            m = fmaf(ri, rj, m);
        }
        sM[tid] = (i == j) ? m : 2.0f * m;
    }
    __syncthreads();

    // ---- loss[n0+k] = (1/(B*H)) * sum_{i<=j} Mfold_ij * Z_ij ----
    auto compute_loss = [&](int k) -> float {
        float s = sM[triidx(6, 6)] * (float)BB;
#pragma unroll
        for (int i = 0; i < 6; i++)
            s = fmaf(sM[triidx(i, 6)], R[6][k + i], s);   // mean terms
#pragma unroll
        for (int i = 0; i < 6; i++)
            s = fmaf(sM[triidx(i, i)], R[0][k + i], s);   // diagonal (lag 0)
#pragma unroll
        for (int i = 0; i < 6; i++)
#pragma unroll
            for (int j = i + 1; j < 6; j++)
                s = fmaf(sM[triidx(i, j)], R[j - i][k + i], s);
        return s * (1.0f / (float)(BB * HID));
    };

    // NPB losses + one neighbor (k = NPB) for the cross-block diff.
    float L = 0.0f;
    const int n = n0 + tid;
    if (tid <= NPB && n < NN) L = compute_loss(tid);
    if (tid <= NPB) sloss[tid] = L;
    __syncthreads();

    if (tid < NPB && n < NN) {
        out[n] = L;
        if (n < NN - 1) {
            const float d = fabsf(sloss[tid + 1] - L);
            out[NN + n] = d;
            out[2 * NN - 1 + n] = (d > __ldg(thr_p)) ? 1.0f : 0.0f;
        }
    }
}

extern "C" void kernel_launch(void* const* d_in, const int* in_sizes, int n_in,
                              void* d_out, int out_size)
{
    const float* series = (const float*)d_in[0];
    const float* weight = (const float*)d_in[1];
    const float* bias   = (const float*)d_in[2];
    const float* thr    = (const float*)d_in[3];
    float* out = (float*)d_out;

    llsa_fused_kernel<<<NBLK, TPB>>>(series, weight, bias, thr, out);
}

// round 9
// speedup vs baseline: 1.6825x; 1.0475x over previous
#include <cuda_runtime.h>

// Problem constants (fixed by the reference)
#define BB   256
#define TT   16384
#define WIN  5
#define HID  5
#define NN   (TT - WIN)   // 16379

// ---- Fused kernel config ----
#define TPB    512                          // 16 warps
#define NPB    120                          // n per block
#define NBLK   ((NN + NPB - 1) / NPB)       // 137 blocks (single wave on 148 SMs)
#define ROWB   136                          // stat row length (padded)
#define NWARP  16
#define RPW    (BB / NWARP)                 // 16 rows per warp
#define NPOOL  8                            // pool slots (two-stage reduce)
#define NSTAT  7                            // C_0..C_5, mean
#define STATF  (NSTAT * ROWB)               // 952 floats

__device__ __forceinline__ int triidx(int i, int j) {
    return 7 * i - (i * (i - 1)) / 2 + (j - i);   // upper-tri 7x7, i <= j
}

__global__ void __launch_bounds__(TPB)
llsa_fused_kernel(const float* __restrict__ series,
                  const float* __restrict__ weight,
                  const float* __restrict__ bias,
                  const float* __restrict__ thr_p,
                  float* __restrict__ out)
{
    __shared__ float pool[NPOOL * STATF];    // 30.5 KB
    __shared__ float R[NSTAT][ROWB + 4];     // reduced stats
    __shared__ float sM[28];
    __shared__ float sloss[NPB + 2];

    const int tid  = threadIdx.x;
    const int slot = tid & 31;        // t4-slot: t-local = slot*4 .. +3
    const int rg   = tid >> 5;        // warp id 0..15 -> rows rg*16 .. rg*16+15
    const int n0   = blockIdx.x * NPB;
    const int tl   = slot * 4;

    float acc[NSTAT][4];
#pragma unroll
    for (int s = 0; s < NSTAT; s++)
#pragma unroll
        for (int i = 0; i < 4; i++) acc[s][i] = 0.0f;

    // ---- Main loop: direct gmem, no smem, no syncs. ----
    const float* base = series + (size_t)(rg * RPW) * TT + (n0 + tl);
    const bool fast = (n0 + tl + 12 <= TT);

    if (fast) {
#pragma unroll 4
        for (int r = 0; r < RPW; r++) {
            const float* rp = base + (size_t)r * TT;
            const float4 a0 = *reinterpret_cast<const float4*>(rp);
            const float4 a1 = *reinterpret_cast<const float4*>(rp + 4);
            const float4 a2 = *reinterpret_cast<const float4*>(rp + 8);
            const float x[9] = {a0.x, a0.y, a0.z, a0.w,
                                a1.x, a1.y, a1.z, a1.w, a2.x};
#pragma unroll
            for (int i = 0; i < 4; i++) {
                acc[6][i] += x[i];
#pragma unroll
                for (int d = 0; d < 6; d++)
                    acc[d][i] = fmaf(x[i], x[i + d], acc[d][i]);
            }
        }
    } else {
        // Last block's high slots only: scalar guarded loads.
        for (int r = 0; r < RPW; r++) {
            const float* rp = base + (size_t)r * TT;
            float x[12];
#pragma unroll
            for (int j = 0; j < 12; j++)
                x[j] = (n0 + tl + j < TT) ? rp[j] : 0.0f;
#pragma unroll
            for (int i = 0; i < 4; i++) {
                acc[6][i] += x[i];
#pragma unroll
                for (int d = 0; d < 6; d++)
                    acc[d][i] = fmaf(x[i], x[i + d], acc[d][i]);
            }
        }
    }

    // ---- Two-stage cross-warp reduction (16 warps -> 8 pool slots -> R) ----
    if (rg >= NPOOL) {
#pragma unroll
        for (int s = 0; s < NSTAT; s++)
#pragma unroll
            for (int i = 0; i < 4; i++)
                pool[(rg - NPOOL) * STATF + s * ROWB + tl + i] = acc[s][i];
    }
    __syncthreads();
    if (rg < NPOOL) {
#pragma unroll
        for (int s = 0; s < NSTAT; s++)
#pragma unroll
            for (int i = 0; i < 4; i++) {
                const int e = rg * STATF + s * ROWB + tl + i;
                pool[e] += acc[s][i];
            }
    }
    __syncthreads();

    for (int e = tid; e < NSTAT * 128; e += TPB) {   // only k<128 is consumed
        const int s = e >> 7;
        const int k = e & 127;
        float v = 0.0f;
#pragma unroll
        for (int w = 0; w < NPOOL; w++)
            v += pool[w * STATF + s * ROWB + k];
        R[s][k] = v;
    }

    // ---- Build folded M: r_h = (W[h,0..4], 0, b_h), r_h[1+h] -= 1 ----
    if (tid < 28) {
        int i = 0, j = tid;
        while (j >= 7 - i) { j -= 7 - i; i++; }
        j += i;
        float m = 0.0f;
#pragma unroll
        for (int h = 0; h < HID; h++) {
            float ri = (i < WIN) ? __ldg(&weight[h * WIN + i]) : 0.0f;
            float rj = (j < WIN) ? __ldg(&weight[h * WIN + j]) : 0.0f;
            if (i == 1 + h) ri -= 1.0f;
            if (j == 1 + h) rj -= 1.0f;
            if (i == 6) ri = __ldg(&bias[h]);
            if (j == 6) rj = __ldg(&bias[h]);
            m = fmaf(ri, rj, m);
        }
        sM[tid] = (i == j) ? m : 2.0f * m;
    }
    __syncthreads();

    // ---- loss[n0+k] = (1/(B*H)) * sum_{i<=j} Mfold_ij * Z_ij ----
    auto compute_loss = [&](int k) -> float {
        float s = sM[triidx(6, 6)] * (float)BB;
#pragma unroll
        for (int i = 0; i < 6; i++)
            s = fmaf(sM[triidx(i, 6)], R[6][k + i], s);   // mean terms
#pragma unroll
        for (int i = 0; i < 6; i++)
            s = fmaf(sM[triidx(i, i)], R[0][k + i], s);   // diagonal (lag 0)
#pragma unroll
        for (int i = 0; i < 6; i++)
#pragma unroll
            for (int j = i + 1; j < 6; j++)
                s = fmaf(sM[triidx(i, j)], R[j - i][k + i], s);
        return s * (1.0f / (float)(BB * HID));
    };

    // NPB losses + one neighbor (k = NPB) for the cross-block diff.
    float L = 0.0f;
    const int n = n0 + tid;
    if (tid <= NPB && n < NN) L = compute_loss(tid);
    if (tid <= NPB) sloss[tid] = L;
    __syncthreads();

    if (tid < NPB && n < NN) {
        out[n] = L;
        if (n < NN - 1) {
            const float d = fabsf(sloss[tid + 1] - L);
            out[NN + n] = d;
            out[2 * NN - 1 + n] = (d > __ldg(thr_p)) ? 1.0f : 0.0f;
        }
    }
}

extern "C" void kernel_launch(void* const* d_in, const int* in_sizes, int n_in,
                              void* d_out, int out_size)
{
    const float* series = (const float*)d_in[0];
    const float* weight = (const float*)d_in[1];
    const float* bias   = (const float*)d_in[2];
    const float* thr    = (const float*)d_in[3];
    float* out = (float*)d_out;

    llsa_fused_kernel<<<NBLK, TPB>>>(series, weight, bias, thr, out);
}